// round 1
// baseline (speedup 1.0000x reference)
#include <cuda_runtime.h>
#include <math.h>

#define DIMS   1024
#define HEADS  16
#define HD     64
#define BATCH  4
#define SEQ    2048
#define TOKENS (BATCH*SEQ)

// Scratch (allocation-free rule: __device__ globals)
__device__ float g_q[(size_t)BATCH*HEADS*SEQ*HD];
__device__ float g_k[(size_t)BATCH*HEADS*SEQ*HD];
__device__ float g_v[(size_t)BATCH*HEADS*SEQ*HD];
__device__ float g_attn[(size_t)TOKENS*DIMS];

// ---------------------------------------------------------------------------
// out = A(MxK) @ W(NxK)^T   (NT gemm, both K-contiguous), M=8192, N=K=1024.
// qkv_mode=1: scatter output into [b,h,n,hd] layout. qkv_mode=0: row-major + bias.
// ---------------------------------------------------------------------------
__global__ __launch_bounds__(256) void gemm_nt(
    const float* __restrict__ A, const float* __restrict__ W,
    float* __restrict__ out, const float* __restrict__ bias, int qkv_mode)
{
    __shared__ float As[16][128];
    __shared__ float Bs[16][128];

    const int tid  = threadIdx.x;
    const int tx   = tid & 15;
    const int ty   = tid >> 4;
    const int row0 = blockIdx.y * 128;
    const int col0 = blockIdx.x * 128;

    const int lr = tid >> 2;         // 0..63
    const int lc = (tid & 3) << 2;   // 0,4,8,12

    float acc[8][8];
    #pragma unroll
    for (int i = 0; i < 8; i++)
        #pragma unroll
        for (int j = 0; j < 8; j++) acc[i][j] = 0.f;

    const float* Ap  = A + (size_t)(row0 + lr) * DIMS + lc;
    const float* Ap2 = Ap + (size_t)64 * DIMS;
    const float* Wp  = W + (size_t)(col0 + lr) * DIMS + lc;
    const float* Wp2 = Wp + (size_t)64 * DIMS;

    for (int k0 = 0; k0 < DIMS; k0 += 16) {
        float4 a0 = *(const float4*)(Ap  + k0);
        float4 a1 = *(const float4*)(Ap2 + k0);
        float4 b0 = *(const float4*)(Wp  + k0);
        float4 b1 = *(const float4*)(Wp2 + k0);
        __syncthreads();
        As[lc+0][lr]    = a0.x; As[lc+1][lr]    = a0.y; As[lc+2][lr]    = a0.z; As[lc+3][lr]    = a0.w;
        As[lc+0][lr+64] = a1.x; As[lc+1][lr+64] = a1.y; As[lc+2][lr+64] = a1.z; As[lc+3][lr+64] = a1.w;
        Bs[lc+0][lr]    = b0.x; Bs[lc+1][lr]    = b0.y; Bs[lc+2][lr]    = b0.z; Bs[lc+3][lr]    = b0.w;
        Bs[lc+0][lr+64] = b1.x; Bs[lc+1][lr+64] = b1.y; Bs[lc+2][lr+64] = b1.z; Bs[lc+3][lr+64] = b1.w;
        __syncthreads();
        #pragma unroll
        for (int kk = 0; kk < 16; kk++) {
            float4 a04 = *(const float4*)&As[kk][ty*8];
            float4 a14 = *(const float4*)&As[kk][ty*8+4];
            float4 b04 = *(const float4*)&Bs[kk][tx*8];
            float4 b14 = *(const float4*)&Bs[kk][tx*8+4];
            float av[8] = {a04.x,a04.y,a04.z,a04.w,a14.x,a14.y,a14.z,a14.w};
            float bv[8] = {b04.x,b04.y,b04.z,b04.w,b14.x,b14.y,b14.z,b14.w};
            #pragma unroll
            for (int i = 0; i < 8; i++)
                #pragma unroll
                for (int j = 0; j < 8; j++)
                    acc[i][j] += av[i] * bv[j];
        }
    }

    if (qkv_mode) {
        #pragma unroll
        for (int i = 0; i < 8; i++) {
            int r = row0 + ty*8 + i;
            int b = r >> 11;          // / SEQ
            int n = r & (SEQ - 1);
            #pragma unroll
            for (int jj = 0; jj < 8; jj += 4) {
                int c = col0 + tx*8 + jj;
                int h = c >> 6;
                int d = c & (HD - 1);
                float4 v = make_float4(acc[i][jj], acc[i][jj+1], acc[i][jj+2], acc[i][jj+3]);
                *(float4*)&out[((size_t)(b*HEADS + h)*SEQ + n)*HD + d] = v;
            }
        }
    } else {
        #pragma unroll
        for (int i = 0; i < 8; i++) {
            int r = row0 + ty*8 + i;
            #pragma unroll
            for (int jj = 0; jj < 8; jj += 4) {
                int c = col0 + tx*8 + jj;
                float4 bb = *(const float4*)&bias[c];
                float4 v = make_float4(acc[i][jj]+bb.x, acc[i][jj+1]+bb.y,
                                       acc[i][jj+2]+bb.z, acc[i][jj+3]+bb.w);
                *(float4*)&out[(size_t)r*DIMS + c] = v;
            }
        }
    }
}

// ---------------------------------------------------------------------------
// Streaming-softmax attention. Block = (64-query tile) x (b*h). 256 threads.
// Thread (qg,kg): qg=tid/16 owns query rows qg*4+i; kg=tid%16 owns k-cols /
// d-cols kg*4+j. Row reductions via shfl over the 16 kg lanes.
// ---------------------------------------------------------------------------
__global__ __launch_bounds__(256) void flash_attn()
{
    extern __shared__ float sm[];
    float (*Qs)[68] = (float (*)[68])(sm);
    float (*Ks)[68] = (float (*)[68])(sm + 64*68);
    float (*Vs)[68] = (float (*)[68])(sm + 2*64*68);
    float (*Ss)[68] = (float (*)[68])(sm + 3*64*68);

    const int tid = threadIdx.x;
    const int bh  = blockIdx.y;
    const int qt  = blockIdx.x;
    const size_t base = (size_t)bh * SEQ * HD;
    const float* Qp = g_q + base + (size_t)qt * 64 * HD;
    const float* Kp = g_k + base;
    const float* Vp = g_v + base;

    const float scale = 0.125f;  // hd^-0.5
    for (int i = tid; i < 64*16; i += 256) {
        int r = i >> 4, c = (i & 15) << 2;
        float4 v = *(const float4*)(Qp + r*HD + c);
        v.x *= scale; v.y *= scale; v.z *= scale; v.w *= scale;
        *(float4*)&Qs[r][c] = v;
    }

    const int qg = tid >> 4;
    const int kg = tid & 15;

    float o[4][4];
    float m_run[4], l_run[4];
    #pragma unroll
    for (int i = 0; i < 4; i++) {
        m_run[i] = -1e30f; l_run[i] = 0.f;
        #pragma unroll
        for (int j = 0; j < 4; j++) o[i][j] = 0.f;
    }

    for (int t = 0; t < SEQ/64; t++) {
        for (int i = tid; i < 64*16; i += 256) {
            int r = i >> 4, c = (i & 15) << 2;
            const float* kptr = Kp + ((size_t)t*64 + r)*HD + c;
            const float* vptr = Vp + ((size_t)t*64 + r)*HD + c;
            *(float4*)&Ks[r][c] = *(const float4*)kptr;
            *(float4*)&Vs[r][c] = *(const float4*)vptr;
        }
        __syncthreads();

        float s[4][4];
        #pragma unroll
        for (int i = 0; i < 4; i++)
            #pragma unroll
            for (int j = 0; j < 4; j++) s[i][j] = 0.f;

        #pragma unroll
        for (int d4 = 0; d4 < 16; d4++) {
            float4 qv[4], kv[4];
            #pragma unroll
            for (int i = 0; i < 4; i++) qv[i] = *(const float4*)&Qs[qg*4+i][d4*4];
            #pragma unroll
            for (int j = 0; j < 4; j++) kv[j] = *(const float4*)&Ks[kg*4+j][d4*4];
            #pragma unroll
            for (int i = 0; i < 4; i++)
                #pragma unroll
                for (int j = 0; j < 4; j++)
                    s[i][j] += qv[i].x*kv[j].x + qv[i].y*kv[j].y
                             + qv[i].z*kv[j].z + qv[i].w*kv[j].w;
        }

        #pragma unroll
        for (int i = 0; i < 4; i++) {
            float mx = fmaxf(fmaxf(s[i][0], s[i][1]), fmaxf(s[i][2], s[i][3]));
            mx = fmaxf(mx, __shfl_xor_sync(0xffffffffu, mx, 1));
            mx = fmaxf(mx, __shfl_xor_sync(0xffffffffu, mx, 2));
            mx = fmaxf(mx, __shfl_xor_sync(0xffffffffu, mx, 4));
            mx = fmaxf(mx, __shfl_xor_sync(0xffffffffu, mx, 8));
            float mnew  = fmaxf(m_run[i], mx);
            float alpha = __expf(m_run[i] - mnew);
            float rs = 0.f;
            #pragma unroll
            for (int j = 0; j < 4; j++) {
                float p = __expf(s[i][j] - mnew);
                s[i][j] = p; rs += p;
            }
            rs += __shfl_xor_sync(0xffffffffu, rs, 1);
            rs += __shfl_xor_sync(0xffffffffu, rs, 2);
            rs += __shfl_xor_sync(0xffffffffu, rs, 4);
            rs += __shfl_xor_sync(0xffffffffu, rs, 8);
            l_run[i] = l_run[i]*alpha + rs;
            m_run[i] = mnew;
            #pragma unroll
            for (int j = 0; j < 4; j++) o[i][j] *= alpha;
            *(float4*)&Ss[qg*4+i][kg*4] = make_float4(s[i][0], s[i][1], s[i][2], s[i][3]);
        }
        __syncwarp();   // Ss rows for this qg are produced within the same warp

        #pragma unroll 4
        for (int k = 0; k < 64; k++) {
            float4 vv = *(const float4*)&Vs[k][kg*4];
            #pragma unroll
            for (int i = 0; i < 4; i++) {
                float p = Ss[qg*4+i][k];
                o[i][0] += p*vv.x; o[i][1] += p*vv.y;
                o[i][2] += p*vv.z; o[i][3] += p*vv.w;
            }
        }
        __syncthreads();  // protect Ks/Vs before next tile's loads
    }

    const int b = bh >> 4, h = bh & 15;
    #pragma unroll
    for (int i = 0; i < 4; i++) {
        float inv = 1.0f / l_run[i];
        int n = qt*64 + qg*4 + i;
        float4 v = make_float4(o[i][0]*inv, o[i][1]*inv, o[i][2]*inv, o[i][3]*inv);
        *(float4*)&g_attn[((size_t)(b*SEQ + n))*DIMS + h*HD + kg*4] = v;
    }
}

// ---------------------------------------------------------------------------
extern "C" void kernel_launch(void* const* d_in, const int* in_sizes, int n_in,
                              void* d_out, int out_size)
{
    (void)in_sizes; (void)n_in; (void)out_size;
    const float* x  = (const float*)d_in[0];
    const float* Wq = (const float*)d_in[1];
    const float* Wk = (const float*)d_in[2];
    const float* Wv = (const float*)d_in[3];
    const float* Wo = (const float*)d_in[4];
    const float* bo = (const float*)d_in[5];
    float* out = (float*)d_out;

    float *qp, *kp, *vp, *ap;
    cudaGetSymbolAddress((void**)&qp, g_q);
    cudaGetSymbolAddress((void**)&kp, g_k);
    cudaGetSymbolAddress((void**)&vp, g_v);
    cudaGetSymbolAddress((void**)&ap, g_attn);

    const int smem_bytes = 4 * 64 * 68 * (int)sizeof(float);  // 69632
    cudaFuncSetAttribute(flash_attn, cudaFuncAttributeMaxDynamicSharedMemorySize, smem_bytes);

    dim3 gg(DIMS/128, TOKENS/128);   // (8, 64)
    gemm_nt<<<gg, 256>>>(x, Wq, qp, nullptr, 1);
    gemm_nt<<<gg, 256>>>(x, Wk, kp, nullptr, 1);
    gemm_nt<<<gg, 256>>>(x, Wv, vp, nullptr, 1);
    flash_attn<<<dim3(SEQ/64, BATCH*HEADS), 256, smem_bytes>>>();
    gemm_nt<<<gg, 256>>>(ap, Wo, out, bo, 0);
}

// round 3
// speedup vs baseline: 1.2709x; 1.2709x over previous
#include <cuda_runtime.h>
#include <cuda_bf16.h>
#include <cstdint>
#include <math.h>

#define DIMS   1024
#define HEADS  16
#define HD     64
#define BATCH  4
#define SEQ    2048
#define TOKENS (BATCH*SEQ)

// Scratch (allocation-free rule: __device__ globals)
__device__ float g_q[(size_t)BATCH*HEADS*SEQ*HD];
__device__ float g_k[(size_t)BATCH*HEADS*SEQ*HD];
__device__ float g_v[(size_t)BATCH*HEADS*SEQ*HD];
__device__ float g_attn[(size_t)TOKENS*DIMS];

// ===========================================================================
// helpers
// ===========================================================================
__device__ __forceinline__ uint32_t smem_u32(const void* p) {
    uint32_t a;
    asm("{ .reg .u64 t; cvta.to.shared.u64 t, %1; cvt.u32.u64 %0, t; }" : "=r"(a) : "l"(p));
    return a;
}

#define LDSM4(r, addr) \
    asm volatile("ldmatrix.sync.aligned.m8n8.x4.shared.b16 {%0,%1,%2,%3}, [%4];" \
        : "=r"((r)[0]), "=r"((r)[1]), "=r"((r)[2]), "=r"((r)[3]) : "r"(addr))
#define LDSM2(r, addr) \
    asm volatile("ldmatrix.sync.aligned.m8n8.x2.shared.b16 {%0,%1}, [%2];" \
        : "=r"((r)[0]), "=r"((r)[1]) : "r"(addr))

#define MMA16816(c, a, b) \
    asm volatile("mma.sync.aligned.m16n8k16.row.col.f32.bf16.bf16.f32 " \
        "{%0,%1,%2,%3}, {%4,%5,%6,%7}, {%8,%9}, {%0,%1,%2,%3};" \
        : "+f"((c)[0]), "+f"((c)[1]), "+f"((c)[2]), "+f"((c)[3]) \
        : "r"((a)[0]), "r"((a)[1]), "r"((a)[2]), "r"((a)[3]), \
          "r"((b)[0]), "r"((b)[1]))

// split one float into bf16 hi + bf16 lo (packed pairs: k-even low half, k-odd high)
__device__ __forceinline__ void split2(float a, float b, uint32_t& h, uint32_t& l) {
    __nv_bfloat16 ha = __float2bfloat16(a);
    __nv_bfloat16 hb = __float2bfloat16(b);
    __nv_bfloat16 la = __float2bfloat16(a - __bfloat162float(ha));
    __nv_bfloat16 lb = __float2bfloat16(b - __bfloat162float(hb));
    h = (uint32_t)__bfloat16_as_ushort(ha) | ((uint32_t)__bfloat16_as_ushort(hb) << 16);
    l = (uint32_t)__bfloat16_as_ushort(la) | ((uint32_t)__bfloat16_as_ushort(lb) << 16);
}

// ===========================================================================
// bf16x3 mma.sync GEMM: out = A(8192x1024) @ W(1024x1024)^T
// CTA 128x128, 256 threads (8 warps, 2x4 warp grid, warp tile 64x32).
// K staged 16 wide, double-buffered SMEM, rows padded to 24 bf16 (48B).
//
// SMEM layout per stage buffer (24576 B, 2 buffers = 49152 B dynamic):
//   AH [128][24] bf16 @ 0      AL @ 6144
//   BH [128][24] bf16 @ 12288  BL @ 18432
// ===========================================================================
#define STAGE_B   24576
#define AH_OFF    0
#define AL_OFF    6144
#define BH_OFF    12288
#define BL_OFF    18432
#define ROW_B     48          // bytes per padded row (24 bf16)
#define GEMM_SMEM (2 * STAGE_B)

__global__ __launch_bounds__(256) void gemm_mma(
    const float* __restrict__ A, const float* __restrict__ W,
    float* __restrict__ out, const float* __restrict__ bias, int qkv_mode)
{
    extern __shared__ char smem[];
    const uint32_t s_base = smem_u32(smem);
    const int tid  = threadIdx.x;
    const int lane = tid & 31;
    const int wid  = tid >> 5;
    const int warp_m = wid & 1;    // 0..1 -> 64-row half
    const int warp_n = wid >> 1;   // 0..3 -> 32-col quarter
    const int row0 = blockIdx.y * 128;
    const int col0 = blockIdx.x * 128;

    // -------- global load mapping: thread -> (row, k-half) --------
    const int lrow  = tid >> 1;     // 0..127
    const int lhalf = tid & 1;      // k offset 0 / 8
    const float* Ag = A + (size_t)(row0 + lrow) * DIMS + lhalf * 8;
    const float* Wg = W + (size_t)(col0 + lrow) * DIMS + lhalf * 8;
    const uint32_t st_off = (uint32_t)(lrow * ROW_B + lhalf * 16);

    // -------- ldmatrix source addresses --------
    uint32_t a_addr[4], b_addr[4];
    #pragma unroll
    for (int mt = 0; mt < 4; mt++)
        a_addr[mt] = s_base + AH_OFF
                   + (uint32_t)((warp_m * 64 + mt * 16 + (lane & 15)) * ROW_B)
                   + (uint32_t)((lane >> 4) * 16);
    #pragma unroll
    for (int nt = 0; nt < 4; nt++)
        b_addr[nt] = s_base + BH_OFF
                   + (uint32_t)((warp_n * 32 + nt * 8 + (lane & 7)) * ROW_B)
                   + (uint32_t)(((lane >> 3) & 1) * 16);

    float acc[4][4][4];
    #pragma unroll
    for (int i = 0; i < 4; i++)
        #pragma unroll
        for (int j = 0; j < 4; j++)
            #pragma unroll
            for (int q = 0; q < 4; q++) acc[i][j][q] = 0.f;

    // -------- stage 0 prefetch + store --------
    float4 pa0 = *(const float4*)(Ag);
    float4 pa1 = *(const float4*)(Ag + 4);
    float4 pb0 = *(const float4*)(Wg);
    float4 pb1 = *(const float4*)(Wg + 4);

    {
        uint4 h, l;
        char* d = smem + st_off;
        split2(pa0.x, pa0.y, h.x, l.x); split2(pa0.z, pa0.w, h.y, l.y);
        split2(pa1.x, pa1.y, h.z, l.z); split2(pa1.z, pa1.w, h.w, l.w);
        *(uint4*)(d + AH_OFF) = h; *(uint4*)(d + AL_OFF) = l;
        split2(pb0.x, pb0.y, h.x, l.x); split2(pb0.z, pb0.w, h.y, l.y);
        split2(pb1.x, pb1.y, h.z, l.z); split2(pb1.z, pb1.w, h.w, l.w);
        *(uint4*)(d + BH_OFF) = h; *(uint4*)(d + BL_OFF) = l;
    }
    __syncthreads();

    const int NSTAGE = DIMS / 16;   // 64
    for (int kb = 0; kb < NSTAGE; kb++) {
        const uint32_t cb = (uint32_t)(kb & 1) * STAGE_B;
        const bool has_next = (kb + 1 < NSTAGE);
        if (has_next) {
            const float* Ap = Ag + (kb + 1) * 16;
            const float* Wp = Wg + (kb + 1) * 16;
            pa0 = *(const float4*)(Ap);  pa1 = *(const float4*)(Ap + 4);
            pb0 = *(const float4*)(Wp);  pb1 = *(const float4*)(Wp + 4);
        }

        // -------- compute current stage --------
        uint32_t ah[4][4], al[4][4], bh[4][2], bl[4][2];
        #pragma unroll
        for (int mt = 0; mt < 4; mt++) {
            LDSM4(ah[mt], a_addr[mt] + cb);
            LDSM4(al[mt], a_addr[mt] + cb + (AL_OFF - AH_OFF));
        }
        #pragma unroll
        for (int nt = 0; nt < 4; nt++) {
            LDSM2(bh[nt], b_addr[nt] + cb);
            LDSM2(bl[nt], b_addr[nt] + cb + (BL_OFF - BH_OFF));
        }
        #pragma unroll
        for (int mt = 0; mt < 4; mt++)
            #pragma unroll
            for (int nt = 0; nt < 4; nt++) {
                MMA16816(acc[mt][nt], ah[mt], bh[nt]);
                MMA16816(acc[mt][nt], ah[mt], bl[nt]);
                MMA16816(acc[mt][nt], al[mt], bh[nt]);
            }

        // -------- store next stage --------
        if (has_next) {
            uint4 h, l;
            char* d = smem + ((kb + 1) & 1) * STAGE_B + st_off;
            split2(pa0.x, pa0.y, h.x, l.x); split2(pa0.z, pa0.w, h.y, l.y);
            split2(pa1.x, pa1.y, h.z, l.z); split2(pa1.z, pa1.w, h.w, l.w);
            *(uint4*)(d + AH_OFF) = h; *(uint4*)(d + AL_OFF) = l;
            split2(pb0.x, pb0.y, h.x, l.x); split2(pb0.z, pb0.w, h.y, l.y);
            split2(pb1.x, pb1.y, h.z, l.z); split2(pb1.z, pb1.w, h.w, l.w);
            *(uint4*)(d + BH_OFF) = h; *(uint4*)(d + BL_OFF) = l;
        }
        __syncthreads();
    }

    // -------- epilogue --------
    const int rbase = row0 + warp_m * 64 + (lane >> 2);
    const int cbase = col0 + warp_n * 32 + (lane & 3) * 2;

    #pragma unroll
    for (int mt = 0; mt < 4; mt++) {
        #pragma unroll
        for (int half = 0; half < 2; half++) {
            const int r = rbase + mt * 16 + half * 8;
            const int b = r >> 11;
            const int n = r & (SEQ - 1);
            #pragma unroll
            for (int nt = 0; nt < 4; nt++) {
                const int c = cbase + nt * 8;
                float2 v = make_float2(acc[mt][nt][half * 2], acc[mt][nt][half * 2 + 1]);
                if (qkv_mode) {
                    const int h = c >> 6;
                    const int d = c & (HD - 1);
                    *(float2*)&out[((size_t)(b * HEADS + h) * SEQ + n) * HD + d] = v;
                } else {
                    v.x += bias[c]; v.y += bias[c + 1];
                    *(float2*)&out[(size_t)r * DIMS + c] = v;
                }
            }
        }
    }
}

// ---------------------------------------------------------------------------
// Streaming-softmax attention (fp32, shared-mem tiled) — unchanged
// ---------------------------------------------------------------------------
__global__ __launch_bounds__(256) void flash_attn()
{
    extern __shared__ float sm[];
    float (*Qs)[68] = (float (*)[68])(sm);
    float (*Ks)[68] = (float (*)[68])(sm + 64*68);
    float (*Vs)[68] = (float (*)[68])(sm + 2*64*68);
    float (*Ss)[68] = (float (*)[68])(sm + 3*64*68);

    const int tid = threadIdx.x;
    const int bh  = blockIdx.y;
    const int qt  = blockIdx.x;
    const size_t base = (size_t)bh * SEQ * HD;
    const float* Qp = g_q + base + (size_t)qt * 64 * HD;
    const float* Kp = g_k + base;
    const float* Vp = g_v + base;

    const float scale = 0.125f;
    for (int i = tid; i < 64*16; i += 256) {
        int r = i >> 4, c = (i & 15) << 2;
        float4 v = *(const float4*)(Qp + r*HD + c);
        v.x *= scale; v.y *= scale; v.z *= scale; v.w *= scale;
        *(float4*)&Qs[r][c] = v;
    }

    const int qg = tid >> 4;
    const int kg = tid & 15;

    float o[4][4];
    float m_run[4], l_run[4];
    #pragma unroll
    for (int i = 0; i < 4; i++) {
        m_run[i] = -1e30f; l_run[i] = 0.f;
        #pragma unroll
        for (int j = 0; j < 4; j++) o[i][j] = 0.f;
    }

    for (int t = 0; t < SEQ/64; t++) {
        for (int i = tid; i < 64*16; i += 256) {
            int r = i >> 4, c = (i & 15) << 2;
            const float* kptr = Kp + ((size_t)t*64 + r)*HD + c;
            const float* vptr = Vp + ((size_t)t*64 + r)*HD + c;
            *(float4*)&Ks[r][c] = *(const float4*)kptr;
            *(float4*)&Vs[r][c] = *(const float4*)vptr;
        }
        __syncthreads();

        float s[4][4];
        #pragma unroll
        for (int i = 0; i < 4; i++)
            #pragma unroll
            for (int j = 0; j < 4; j++) s[i][j] = 0.f;

        #pragma unroll
        for (int d4 = 0; d4 < 16; d4++) {
            float4 qv[4], kv[4];
            #pragma unroll
            for (int i = 0; i < 4; i++) qv[i] = *(const float4*)&Qs[qg*4+i][d4*4];
            #pragma unroll
            for (int j = 0; j < 4; j++) kv[j] = *(const float4*)&Ks[kg*4+j][d4*4];
            #pragma unroll
            for (int i = 0; i < 4; i++)
                #pragma unroll
                for (int j = 0; j < 4; j++)
                    s[i][j] += qv[i].x*kv[j].x + qv[i].y*kv[j].y
                             + qv[i].z*kv[j].z + qv[i].w*kv[j].w;
        }

        #pragma unroll
        for (int i = 0; i < 4; i++) {
            float mx = fmaxf(fmaxf(s[i][0], s[i][1]), fmaxf(s[i][2], s[i][3]));
            mx = fmaxf(mx, __shfl_xor_sync(0xffffffffu, mx, 1));
            mx = fmaxf(mx, __shfl_xor_sync(0xffffffffu, mx, 2));
            mx = fmaxf(mx, __shfl_xor_sync(0xffffffffu, mx, 4));
            mx = fmaxf(mx, __shfl_xor_sync(0xffffffffu, mx, 8));
            float mnew  = fmaxf(m_run[i], mx);
            float alpha = __expf(m_run[i] - mnew);
            float rs = 0.f;
            #pragma unroll
            for (int j = 0; j < 4; j++) {
                float p = __expf(s[i][j] - mnew);
                s[i][j] = p; rs += p;
            }
            rs += __shfl_xor_sync(0xffffffffu, rs, 1);
            rs += __shfl_xor_sync(0xffffffffu, rs, 2);
            rs += __shfl_xor_sync(0xffffffffu, rs, 4);
            rs += __shfl_xor_sync(0xffffffffu, rs, 8);
            l_run[i] = l_run[i]*alpha + rs;
            m_run[i] = mnew;
            #pragma unroll
            for (int j = 0; j < 4; j++) o[i][j] *= alpha;
            *(float4*)&Ss[qg*4+i][kg*4] = make_float4(s[i][0], s[i][1], s[i][2], s[i][3]);
        }
        __syncwarp();

        #pragma unroll 4
        for (int k = 0; k < 64; k++) {
            float4 vv = *(const float4*)&Vs[k][kg*4];
            #pragma unroll
            for (int i = 0; i < 4; i++) {
                float p = Ss[qg*4+i][k];
                o[i][0] += p*vv.x; o[i][1] += p*vv.y;
                o[i][2] += p*vv.z; o[i][3] += p*vv.w;
            }
        }
        __syncthreads();
    }

    const int b = bh >> 4, h = bh & 15;
    #pragma unroll
    for (int i = 0; i < 4; i++) {
        float inv = 1.0f / l_run[i];
        int n = qt*64 + qg*4 + i;
        float4 v = make_float4(o[i][0]*inv, o[i][1]*inv, o[i][2]*inv, o[i][3]*inv);
        *(float4*)&g_attn[((size_t)(b*SEQ + n))*DIMS + h*HD + kg*4] = v;
    }
}

// ---------------------------------------------------------------------------
extern "C" void kernel_launch(void* const* d_in, const int* in_sizes, int n_in,
                              void* d_out, int out_size)
{
    (void)in_sizes; (void)n_in; (void)out_size;
    const float* x  = (const float*)d_in[0];
    const float* Wq = (const float*)d_in[1];
    const float* Wk = (const float*)d_in[2];
    const float* Wv = (const float*)d_in[3];
    const float* Wo = (const float*)d_in[4];
    const float* bo = (const float*)d_in[5];
    float* out = (float*)d_out;

    float *qp, *kp, *vp, *ap;
    cudaGetSymbolAddress((void**)&qp, g_q);
    cudaGetSymbolAddress((void**)&kp, g_k);
    cudaGetSymbolAddress((void**)&vp, g_v);
    cudaGetSymbolAddress((void**)&ap, g_attn);

    const int attn_smem = 4 * 64 * 68 * (int)sizeof(float);  // 69632
    cudaFuncSetAttribute(flash_attn, cudaFuncAttributeMaxDynamicSharedMemorySize, attn_smem);
    cudaFuncSetAttribute(gemm_mma, cudaFuncAttributeMaxDynamicSharedMemorySize, GEMM_SMEM);

    dim3 gg(DIMS/128, TOKENS/128);   // (8, 64)
    gemm_mma<<<gg, 256, GEMM_SMEM>>>(x, Wq, qp, nullptr, 1);
    gemm_mma<<<gg, 256, GEMM_SMEM>>>(x, Wk, kp, nullptr, 1);
    gemm_mma<<<gg, 256, GEMM_SMEM>>>(x, Wv, vp, nullptr, 1);
    flash_attn<<<dim3(SEQ/64, BATCH*HEADS), 256, attn_smem>>>();
    gemm_mma<<<gg, 256, GEMM_SMEM>>>(ap, Wo, out, bo, 0);
}

// round 5
// speedup vs baseline: 3.6420x; 2.8657x over previous
#include <cuda_runtime.h>
#include <cuda_bf16.h>
#include <cstdint>
#include <math.h>

#define DIMS   1024
#define HEADS  16
#define HD     64
#define BATCH  4
#define SEQ    2048
#define TOKENS (BATCH*SEQ)

// Scratch (allocation-free rule: __device__ globals)
// Q/K/V stored as pre-split bf16 hi/lo planes, layout [b,h,n,hd]
__device__ __nv_bfloat16 g_qh[(size_t)BATCH*HEADS*SEQ*HD];
__device__ __nv_bfloat16 g_ql[(size_t)BATCH*HEADS*SEQ*HD];
__device__ __nv_bfloat16 g_kh[(size_t)BATCH*HEADS*SEQ*HD];
__device__ __nv_bfloat16 g_kl[(size_t)BATCH*HEADS*SEQ*HD];
__device__ __nv_bfloat16 g_vh[(size_t)BATCH*HEADS*SEQ*HD];
__device__ __nv_bfloat16 g_vl[(size_t)BATCH*HEADS*SEQ*HD];
__device__ float g_attn[(size_t)TOKENS*DIMS];

// ===========================================================================
// helpers
// ===========================================================================
__device__ __forceinline__ uint32_t smem_u32(const void* p) {
    uint32_t a;
    asm("{ .reg .u64 t; cvta.to.shared.u64 t, %1; cvt.u32.u64 %0, t; }" : "=r"(a) : "l"(p));
    return a;
}

#define LDSM4(r, addr) \
    asm volatile("ldmatrix.sync.aligned.m8n8.x4.shared.b16 {%0,%1,%2,%3}, [%4];" \
        : "=r"((r)[0]), "=r"((r)[1]), "=r"((r)[2]), "=r"((r)[3]) : "r"(addr))
#define LDSM4T(r, addr) \
    asm volatile("ldmatrix.sync.aligned.m8n8.x4.trans.shared.b16 {%0,%1,%2,%3}, [%4];" \
        : "=r"((r)[0]), "=r"((r)[1]), "=r"((r)[2]), "=r"((r)[3]) : "r"(addr))
#define LDSM2(r, addr) \
    asm volatile("ldmatrix.sync.aligned.m8n8.x2.shared.b16 {%0,%1}, [%2];" \
        : "=r"((r)[0]), "=r"((r)[1]) : "r"(addr))

#define MMA16816(c, a, b) \
    asm volatile("mma.sync.aligned.m16n8k16.row.col.f32.bf16.bf16.f32 " \
        "{%0,%1,%2,%3}, {%4,%5,%6,%7}, {%8,%9}, {%0,%1,%2,%3};" \
        : "+f"((c)[0]), "+f"((c)[1]), "+f"((c)[2]), "+f"((c)[3]) \
        : "r"((a)[0]), "r"((a)[1]), "r"((a)[2]), "r"((a)[3]), \
          "r"((b)[0]), "r"((b)[1]))

__device__ __forceinline__ uint32_t pack_bf2(float hi, float lo) {
    uint32_t r;
    asm("cvt.rn.bf16x2.f32 %0, %1, %2;" : "=r"(r) : "f"(hi), "f"(lo));
    return r;
}

__device__ __forceinline__ void split2(float a, float b, uint32_t& h, uint32_t& l) {
    h = pack_bf2(b, a);
    float h0 = __uint_as_float(h << 16);
    float h1 = __uint_as_float(h & 0xffff0000u);
    l = pack_bf2(b - h1, a - h0);
}

__device__ __forceinline__ void cp16(uint32_t dst, const void* src) {
    asm volatile("cp.async.ca.shared.global [%0], [%1], 16;" :: "r"(dst), "l"(src));
}
#define CP_COMMIT() asm volatile("cp.async.commit_group;" ::: "memory")
#define CP_WAIT0()  asm volatile("cp.async.wait_group 0;" ::: "memory")
#define CP_WAIT1()  asm volatile("cp.async.wait_group 1;" ::: "memory")

// ===========================================================================
// bf16x3 mma.sync GEMM: out = A(8192x1024) @ W(1024x1024)^T
// mode 0: fp32 out + bias. mode 1: bf16 hi/lo planes [b,h,n,hd], scaled.
// ===========================================================================
#define STAGE_B   24576
#define AH_OFF    0
#define AL_OFF    6144
#define BH_OFF    12288
#define BL_OFF    18432
#define ROW_B     48
#define GEMM_SMEM (2 * STAGE_B)

__global__ __launch_bounds__(256) void gemm_mma(
    const float* __restrict__ A, const float* __restrict__ W,
    float* __restrict__ outf, __nv_bfloat16* __restrict__ oh,
    __nv_bfloat16* __restrict__ ol, const float* __restrict__ bias,
    float scale, int qkv_mode)
{
    extern __shared__ char smem[];
    const uint32_t s_base = smem_u32(smem);
    const int tid  = threadIdx.x;
    const int lane = tid & 31;
    const int wid  = tid >> 5;
    const int warp_m = wid & 1;
    const int warp_n = wid >> 1;
    const int row0 = blockIdx.y * 128;
    const int col0 = blockIdx.x * 128;

    const int lrow  = tid >> 1;
    const int lhalf = tid & 1;
    const float* Ag = A + (size_t)(row0 + lrow) * DIMS + lhalf * 8;
    const float* Wg = W + (size_t)(col0 + lrow) * DIMS + lhalf * 8;
    const uint32_t st_off = (uint32_t)(lrow * ROW_B + lhalf * 16);

    uint32_t a_addr[4], b_addr[4];
    #pragma unroll
    for (int mt = 0; mt < 4; mt++)
        a_addr[mt] = s_base + AH_OFF
                   + (uint32_t)((warp_m * 64 + mt * 16 + (lane & 15)) * ROW_B)
                   + (uint32_t)((lane >> 4) * 16);
    #pragma unroll
    for (int nt = 0; nt < 4; nt++)
        b_addr[nt] = s_base + BH_OFF
                   + (uint32_t)((warp_n * 32 + nt * 8 + (lane & 7)) * ROW_B)
                   + (uint32_t)(((lane >> 3) & 1) * 16);

    float acc[4][4][4];
    #pragma unroll
    for (int i = 0; i < 4; i++)
        #pragma unroll
        for (int j = 0; j < 4; j++)
            #pragma unroll
            for (int q = 0; q < 4; q++) acc[i][j][q] = 0.f;

    float4 pa0 = *(const float4*)(Ag);
    float4 pa1 = *(const float4*)(Ag + 4);
    float4 pb0 = *(const float4*)(Wg);
    float4 pb1 = *(const float4*)(Wg + 4);

    {
        uint4 h, l;
        char* d = smem + st_off;
        split2(pa0.x, pa0.y, h.x, l.x); split2(pa0.z, pa0.w, h.y, l.y);
        split2(pa1.x, pa1.y, h.z, l.z); split2(pa1.z, pa1.w, h.w, l.w);
        *(uint4*)(d + AH_OFF) = h; *(uint4*)(d + AL_OFF) = l;
        split2(pb0.x, pb0.y, h.x, l.x); split2(pb0.z, pb0.w, h.y, l.y);
        split2(pb1.x, pb1.y, h.z, l.z); split2(pb1.z, pb1.w, h.w, l.w);
        *(uint4*)(d + BH_OFF) = h; *(uint4*)(d + BL_OFF) = l;
    }
    __syncthreads();

    const int NSTAGE = DIMS / 16;
    for (int kb = 0; kb < NSTAGE; kb++) {
        const uint32_t cb = (uint32_t)(kb & 1) * STAGE_B;
        const bool has_next = (kb + 1 < NSTAGE);
        if (has_next) {
            const float* Ap = Ag + (kb + 1) * 16;
            const float* Wp = Wg + (kb + 1) * 16;
            pa0 = *(const float4*)(Ap);  pa1 = *(const float4*)(Ap + 4);
            pb0 = *(const float4*)(Wp);  pb1 = *(const float4*)(Wp + 4);
        }

        uint32_t ah[4][4], al[4][4], bh[4][2], bl[4][2];
        #pragma unroll
        for (int mt = 0; mt < 4; mt++) {
            LDSM4(ah[mt], a_addr[mt] + cb);
            LDSM4(al[mt], a_addr[mt] + cb + (AL_OFF - AH_OFF));
        }
        #pragma unroll
        for (int nt = 0; nt < 4; nt++) {
            LDSM2(bh[nt], b_addr[nt] + cb);
            LDSM2(bl[nt], b_addr[nt] + cb + (BL_OFF - BH_OFF));
        }
        #pragma unroll
        for (int mt = 0; mt < 4; mt++)
            #pragma unroll
            for (int nt = 0; nt < 4; nt++) {
                MMA16816(acc[mt][nt], ah[mt], bh[nt]);
                MMA16816(acc[mt][nt], ah[mt], bl[nt]);
                MMA16816(acc[mt][nt], al[mt], bh[nt]);
            }

        if (has_next) {
            uint4 h, l;
            char* d = smem + ((kb + 1) & 1) * STAGE_B + st_off;
            split2(pa0.x, pa0.y, h.x, l.x); split2(pa0.z, pa0.w, h.y, l.y);
            split2(pa1.x, pa1.y, h.z, l.z); split2(pa1.z, pa1.w, h.w, l.w);
            *(uint4*)(d + AH_OFF) = h; *(uint4*)(d + AL_OFF) = l;
            split2(pb0.x, pb0.y, h.x, l.x); split2(pb0.z, pb0.w, h.y, l.y);
            split2(pb1.x, pb1.y, h.z, l.z); split2(pb1.z, pb1.w, h.w, l.w);
            *(uint4*)(d + BH_OFF) = h; *(uint4*)(d + BL_OFF) = l;
        }
        __syncthreads();
    }

    const int rbase = row0 + warp_m * 64 + (lane >> 2);
    const int cbase = col0 + warp_n * 32 + (lane & 3) * 2;

    #pragma unroll
    for (int mt = 0; mt < 4; mt++) {
        #pragma unroll
        for (int half = 0; half < 2; half++) {
            const int r = rbase + mt * 16 + half * 8;
            const int b = r >> 11;
            const int n = r & (SEQ - 1);
            #pragma unroll
            for (int nt = 0; nt < 4; nt++) {
                const int c = cbase + nt * 8;
                float vx = acc[mt][nt][half * 2];
                float vy = acc[mt][nt][half * 2 + 1];
                if (qkv_mode) {
                    vx *= scale; vy *= scale;
                    const int h = c >> 6;
                    const int d = c & (HD - 1);
                    const size_t idx = ((size_t)(b * HEADS + h) * SEQ + n) * HD + d;
                    uint32_t hp, lp;
                    split2(vx, vy, hp, lp);
                    *(uint32_t*)&oh[idx] = hp;
                    *(uint32_t*)&ol[idx] = lp;
                } else {
                    vx += bias[c]; vy += bias[c + 1];
                    *(float2*)&outf[(size_t)r * DIMS + c] = make_float2(vx, vy);
                }
            }
        }
    }
}

// ===========================================================================
// Flash attention with mma.sync bf16 hi/lo split.
// CTA: 64 q-rows x one (b,h). 128 threads = 4 warps, warp = 16 q-rows.
// KV tiles of 64, cp.async double-buffered.
// SMEM: Qh/Ql [64][144B] @ 0/9216; KV buffers: {Kh,Kl,Vh,Vl}[64][144B] x2
// ===========================================================================
#define ROWB     144
#define KV_PLANE (64*ROWB)              // 9216
#define Q_SMEM   (2*KV_PLANE)           // 18432
#define KV_BUF   (4*KV_PLANE)           // 36864
#define ATT_SMEM (Q_SMEM + 2*KV_BUF)    // 92160

__global__ __launch_bounds__(128) void flash_mma()
{
    extern __shared__ char smf[];
    const uint32_t sb = smem_u32(smf);
    const int tid  = threadIdx.x;
    const int lane = tid & 31;
    const int w    = tid >> 5;
    const int qt   = blockIdx.x;
    const int bh   = blockIdx.y;
    const size_t base = (size_t)bh * SEQ * HD;

    const int row  = tid >> 1;     // 0..63
    const int half = tid & 1;      // 64B half of 128B row

    // ---- load Q hi/lo planes into smem ----
    {
        const size_t qoff = base + ((size_t)(qt * 64 + row)) * HD + half * 32;
        const __nv_bfloat16* qh_g = g_qh + qoff;
        const __nv_bfloat16* ql_g = g_ql + qoff;
        char* dh = smf + row * ROWB + half * 64;
        char* dl = smf + KV_PLANE + row * ROWB + half * 64;
        #pragma unroll
        for (int i = 0; i < 4; i++) {
            *(uint4*)(dh + i * 16) = *(const uint4*)(qh_g + i * 8);
            *(uint4*)(dl + i * 16) = *(const uint4*)(ql_g + i * 8);
        }
    }

    // ---- cp.async issue helper (tile -> buffer) ----
    const __nv_bfloat16* kv_src[4] = { g_kh + base, g_kl + base, g_vh + base, g_vl + base };
    const uint32_t row_half_off = (uint32_t)(row * ROWB + half * 64);

    // prologue: issue tiles 0 and 1
    #pragma unroll
    for (int pre = 0; pre < 2; pre++) {
        const uint32_t dbase = sb + Q_SMEM + pre * KV_BUF;
        const size_t soff = ((size_t)(pre * 64 + row)) * HD + half * 32;
        #pragma unroll
        for (int p = 0; p < 4; p++) {
            const __nv_bfloat16* src = kv_src[p] + soff;
            const uint32_t dst = dbase + p * KV_PLANE + row_half_off;
            cp16(dst,      src);
            cp16(dst + 16, src + 8);
            cp16(dst + 32, src + 16);
            cp16(dst + 48, src + 24);
        }
        CP_COMMIT();
    }

    __syncthreads();   // Q smem ready

    // ---- Q fragments to registers ----
    uint32_t qh[4][4], ql[4][4];
    {
        const uint32_t qlane = (uint32_t)((w * 16 + (lane & 15)) * ROWB + (lane >> 4) * 16);
        #pragma unroll
        for (int kk = 0; kk < 4; kk++) {
            LDSM4(qh[kk], sb + qlane + kk * 32);
            LDSM4(ql[kk], sb + KV_PLANE + qlane + kk * 32);
        }
    }

    // lane-dependent ldmatrix offsets
    const int g8 = lane >> 3;   // address group 0..3
    const uint32_t klane = (uint32_t)((8 * (g8 >> 1) + (lane & 7)) * ROWB + (g8 & 1) * 16);
    const uint32_t vlane = (uint32_t)(((lane & 7) + (g8 & 1) * 8) * ROWB + (g8 >> 1) * 16);

    float oc[8][4];
    #pragma unroll
    for (int j = 0; j < 8; j++)
        #pragma unroll
        for (int q = 0; q < 4; q++) oc[j][q] = 0.f;
    float m0 = -1e30f, m1 = -1e30f, l0 = 0.f, l1 = 0.f;

    const int NT = SEQ / 64;   // 32
    for (int t = 0; t < NT; t++) {
        if (t < NT - 1) { CP_WAIT1(); } else { CP_WAIT0(); }
        __syncthreads();

        const uint32_t kvb = sb + Q_SMEM + (uint32_t)(t & 1) * KV_BUF;
        const uint32_t Kh_b = kvb;
        const uint32_t Kl_b = kvb + KV_PLANE;
        const uint32_t Vh_b = kvb + 2 * KV_PLANE;
        const uint32_t Vl_b = kvb + 3 * KV_PLANE;

        // ---- S = Q K^T (split bf16, 3 products) ----
        float sc[8][4];
        #pragma unroll
        for (int j = 0; j < 8; j++)
            #pragma unroll
            for (int q = 0; q < 4; q++) sc[j][q] = 0.f;

        #pragma unroll
        for (int kk = 0; kk < 4; kk++) {
            #pragma unroll
            for (int jp = 0; jp < 4; jp++) {
                uint32_t kh4[4], kl4[4];
                const uint32_t ka = jp * (16 * ROWB) + kk * 32 + klane;
                LDSM4(kh4, Kh_b + ka);
                LDSM4(kl4, Kl_b + ka);
                MMA16816(sc[2*jp],   qh[kk], kh4 + 0);
                MMA16816(sc[2*jp],   qh[kk], kl4 + 0);
                MMA16816(sc[2*jp],   ql[kk], kh4 + 0);
                MMA16816(sc[2*jp+1], qh[kk], kh4 + 2);
                MMA16816(sc[2*jp+1], qh[kk], kl4 + 2);
                MMA16816(sc[2*jp+1], ql[kk], kh4 + 2);
            }
        }

        // ---- online softmax (rows: g = lane>>2 and g+8) ----
        float mx0 = -1e30f, mx1 = -1e30f;
        #pragma unroll
        for (int j = 0; j < 8; j++) {
            mx0 = fmaxf(mx0, fmaxf(sc[j][0], sc[j][1]));
            mx1 = fmaxf(mx1, fmaxf(sc[j][2], sc[j][3]));
        }
        mx0 = fmaxf(mx0, __shfl_xor_sync(0xffffffffu, mx0, 1));
        mx0 = fmaxf(mx0, __shfl_xor_sync(0xffffffffu, mx0, 2));
        mx1 = fmaxf(mx1, __shfl_xor_sync(0xffffffffu, mx1, 1));
        mx1 = fmaxf(mx1, __shfl_xor_sync(0xffffffffu, mx1, 2));

        const float mn0 = fmaxf(m0, mx0);
        const float mn1 = fmaxf(m1, mx1);
        const float al0 = __expf(m0 - mn0);
        const float al1 = __expf(m1 - mn1);
        m0 = mn0; m1 = mn1;

        float rs0 = 0.f, rs1 = 0.f;
        #pragma unroll
        for (int j = 0; j < 8; j++) {
            sc[j][0] = __expf(sc[j][0] - mn0); rs0 += sc[j][0];
            sc[j][1] = __expf(sc[j][1] - mn0); rs0 += sc[j][1];
            sc[j][2] = __expf(sc[j][2] - mn1); rs1 += sc[j][2];
            sc[j][3] = __expf(sc[j][3] - mn1); rs1 += sc[j][3];
        }
        rs0 += __shfl_xor_sync(0xffffffffu, rs0, 1);
        rs0 += __shfl_xor_sync(0xffffffffu, rs0, 2);
        rs1 += __shfl_xor_sync(0xffffffffu, rs1, 1);
        rs1 += __shfl_xor_sync(0xffffffffu, rs1, 2);
        l0 = l0 * al0 + rs0;
        l1 = l1 * al1 + rs1;

        #pragma unroll
        for (int j = 0; j < 8; j++) {
            oc[j][0] *= al0; oc[j][1] *= al0;
            oc[j][2] *= al1; oc[j][3] *= al1;
        }

        // ---- O += P V (split bf16, 3 products) ----
        #pragma unroll
        for (int tt = 0; tt < 4; tt++) {
            uint32_t pah[4], pal[4];
            #pragma unroll
            for (int q = 0; q < 2; q++) {
                const float c0a = sc[2*tt + q][0], c1a = sc[2*tt + q][1];
                const float c2a = sc[2*tt + q][2], c3a = sc[2*tt + q][3];
                uint32_t hp, lp;
                split2(c0a, c1a, hp, lp);
                pah[2*q]     = hp; pal[2*q]     = lp;
                split2(c2a, c3a, hp, lp);
                pah[2*q + 1] = hp; pal[2*q + 1] = lp;
            }
            #pragma unroll
            for (int dp = 0; dp < 4; dp++) {
                uint32_t vh4[4], vl4[4];
                const uint32_t va = tt * (16 * ROWB) + dp * 32 + vlane;
                LDSM4T(vh4, Vh_b + va);
                LDSM4T(vl4, Vl_b + va);
                MMA16816(oc[2*dp],   pah, vh4 + 0);
                MMA16816(oc[2*dp],   pah, vl4 + 0);
                MMA16816(oc[2*dp],   pal, vh4 + 0);
                MMA16816(oc[2*dp+1], pah, vh4 + 2);
                MMA16816(oc[2*dp+1], pah, vl4 + 2);
                MMA16816(oc[2*dp+1], pal, vh4 + 2);
            }
        }

        __syncthreads();   // done reading this buffer

        // issue tile t+2 into the buffer just consumed
        if (t + 2 < NT) {
            const uint32_t dbase = sb + Q_SMEM + (uint32_t)(t & 1) * KV_BUF;
            const size_t soff = ((size_t)((t + 2) * 64 + row)) * HD + half * 32;
            #pragma unroll
            for (int p = 0; p < 4; p++) {
                const __nv_bfloat16* src = kv_src[p] + soff;
                const uint32_t dst = dbase + p * KV_PLANE + row_half_off;
                cp16(dst,      src);
                cp16(dst + 16, src + 8);
                cp16(dst + 32, src + 16);
                cp16(dst + 48, src + 24);
            }
            CP_COMMIT();
        }
    }

    // ---- epilogue ----
    const int g  = lane >> 2;
    const int tg = lane & 3;
    const int b  = bh >> 4;
    const int h  = bh & 15;
    const int n0 = qt * 64 + w * 16 + g;
    const float inv0 = 1.0f / l0;
    const float inv1 = 1.0f / l1;
    #pragma unroll
    for (int j = 0; j < 8; j++) {
        const int c = h * HD + j * 8 + tg * 2;
        *(float2*)&g_attn[(size_t)(b * SEQ + n0) * DIMS + c] =
            make_float2(oc[j][0] * inv0, oc[j][1] * inv0);
        *(float2*)&g_attn[(size_t)(b * SEQ + n0 + 8) * DIMS + c] =
            make_float2(oc[j][2] * inv1, oc[j][3] * inv1);
    }
}

// ---------------------------------------------------------------------------
extern "C" void kernel_launch(void* const* d_in, const int* in_sizes, int n_in,
                              void* d_out, int out_size)
{
    (void)in_sizes; (void)n_in; (void)out_size;
    const float* x  = (const float*)d_in[0];
    const float* Wq = (const float*)d_in[1];
    const float* Wk = (const float*)d_in[2];
    const float* Wv = (const float*)d_in[3];
    const float* Wo = (const float*)d_in[4];
    const float* bo = (const float*)d_in[5];
    float* out = (float*)d_out;

    __nv_bfloat16 *qh, *ql, *kh, *kl, *vh, *vl;
    float* ap;
    cudaGetSymbolAddress((void**)&qh, g_qh);
    cudaGetSymbolAddress((void**)&ql, g_ql);
    cudaGetSymbolAddress((void**)&kh, g_kh);
    cudaGetSymbolAddress((void**)&kl, g_kl);
    cudaGetSymbolAddress((void**)&vh, g_vh);
    cudaGetSymbolAddress((void**)&vl, g_vl);
    cudaGetSymbolAddress((void**)&ap, g_attn);

    cudaFuncSetAttribute(gemm_mma, cudaFuncAttributeMaxDynamicSharedMemorySize, GEMM_SMEM);
    cudaFuncSetAttribute(flash_mma, cudaFuncAttributeMaxDynamicSharedMemorySize, ATT_SMEM);

    dim3 gg(DIMS/128, TOKENS/128);   // (8, 64)
    gemm_mma<<<gg, 256, GEMM_SMEM>>>(x, Wq, nullptr, qh, ql, nullptr, 0.125f, 1);
    gemm_mma<<<gg, 256, GEMM_SMEM>>>(x, Wk, nullptr, kh, kl, nullptr, 1.0f, 1);
    gemm_mma<<<gg, 256, GEMM_SMEM>>>(x, Wv, nullptr, vh, vl, nullptr, 1.0f, 1);
    flash_mma<<<dim3(SEQ/64, BATCH*HEADS), 128, ATT_SMEM>>>();
    gemm_mma<<<gg, 256, GEMM_SMEM>>>(ap, Wo, out, nullptr, nullptr, bo, 1.0f, 0);
}